// round 7
// baseline (speedup 1.0000x reference)
#include <cuda_runtime.h>
#include <cuda_bf16.h>
#include <stdint.h>

#define B_   8
#define T_   2048
#define D_   1024
#define KQ_  128
#define TOPK 8
#define TOPN 12            // approx candidates tracked per row
#define BT_  (B_ * T_)

#define GATH_N ((size_t)BT_ * TOPK * D_)   // 134217728
#define IDX_N  ((size_t)BT_ * TOPK)        // 131072

// Scratch (__device__ globals; allocation-free rule)
__device__ float g_q[BT_ * KQ_];
__device__ float g_k[BT_ * KQ_];
__device__ int   g_idx[BT_ * TOPK];
__device__ int   g_cand[BT_ * TOPN];

// ---------------------------------------------------------------------------
// Kernel A: proj — VERBATIM the R1 kernel that passed (bit-identical q/k).
// GEMM M=16384, N=256 (q||k), K=1024.  BM=64, BN=256, BK=32; 256 thr; 8x8.
// Per-output FMA chain is k-ascending -> deterministic fp32 draw (known good).
// ---------------------------------------------------------------------------
__global__ __launch_bounds__(256) void proj_kernel(
    const float* __restrict__ x,
    const float* __restrict__ Wq, const float* __restrict__ bq,
    const float* __restrict__ Wk, const float* __restrict__ bk)
{
    __shared__ float As[32][68];
    __shared__ float Bs[32][260];

    const int tid = threadIdx.x;
    const int m0  = blockIdx.x * 64;
    const int ty  = tid >> 5;
    const int tx  = tid & 31;

    float acc[8][8];
#pragma unroll
    for (int i = 0; i < 8; i++)
#pragma unroll
        for (int j = 0; j < 8; j++) acc[i][j] = 0.f;

    for (int k0 = 0; k0 < D_; k0 += 32) {
#pragma unroll
        for (int l = 0; l < 2; l++) {
            int e  = tid + l * 256;
            int r  = e >> 3;
            int c4 = e & 7;
            float4 v = *reinterpret_cast<const float4*>(
                &x[(size_t)(m0 + r) * D_ + k0 + c4 * 4]);
            As[c4 * 4 + 0][r] = v.x;
            As[c4 * 4 + 1][r] = v.y;
            As[c4 * 4 + 2][r] = v.z;
            As[c4 * 4 + 3][r] = v.w;
        }
#pragma unroll
        for (int l = 0; l < 8; l++) {
            int e  = tid + l * 256;
            int n  = e >> 3;
            int c4 = e & 7;
            const float* Wsrc = (n < 128) ? &Wq[(size_t)n * D_]
                                          : &Wk[(size_t)(n - 128) * D_];
            float4 v = *reinterpret_cast<const float4*>(&Wsrc[k0 + c4 * 4]);
            Bs[c4 * 4 + 0][n] = v.x;
            Bs[c4 * 4 + 1][n] = v.y;
            Bs[c4 * 4 + 2][n] = v.z;
            Bs[c4 * 4 + 3][n] = v.w;
        }
        __syncthreads();

#pragma unroll 4
        for (int d = 0; d < 32; d++) {
            float4 a0 = *reinterpret_cast<const float4*>(&As[d][ty * 8]);
            float4 a1 = *reinterpret_cast<const float4*>(&As[d][ty * 8 + 4]);
            float4 b0 = *reinterpret_cast<const float4*>(&Bs[d][tx * 8]);
            float4 b1 = *reinterpret_cast<const float4*>(&Bs[d][tx * 8 + 4]);
            float a[8] = {a0.x, a0.y, a0.z, a0.w, a1.x, a1.y, a1.z, a1.w};
            float b[8] = {b0.x, b0.y, b0.z, b0.w, b1.x, b1.y, b1.z, b1.w};
#pragma unroll
            for (int i = 0; i < 8; i++)
#pragma unroll
                for (int j = 0; j < 8; j++) acc[i][j] += a[i] * b[j];
        }
        __syncthreads();
    }

    float* dst;
    const float* bias;
    int n0;
    if (tx < 16) { dst = g_q; bias = bq; n0 = tx * 8; }
    else         { dst = g_k; bias = bk; n0 = (tx - 16) * 8; }
    float bb[8];
#pragma unroll
    for (int j = 0; j < 8; j++) bb[j] = bias[n0 + j];

#pragma unroll
    for (int i = 0; i < 8; i++) {
        int m = m0 + ty * 8 + i;
        float4 v0 = make_float4(acc[i][0] + bb[0], acc[i][1] + bb[1],
                                acc[i][2] + bb[2], acc[i][3] + bb[3]);
        float4 v1 = make_float4(acc[i][4] + bb[4], acc[i][5] + bb[5],
                                acc[i][6] + bb[6], acc[i][7] + bb[7]);
        *reinterpret_cast<float4*>(&dst[(size_t)m * KQ_ + n0])     = v0;
        *reinterpret_cast<float4*>(&dst[(size_t)m * KQ_ + n0 + 4]) = v1;
    }
}

// ---------------------------------------------------------------------------
// Approx sim helpers (2-plane bf16 split; 3 MMA terms -> |err| <~ 5e-5,
// vastly below typical top-k gaps ~0.19; only candidate SET matters).
// ---------------------------------------------------------------------------
__device__ __forceinline__ void split2f(float v, float& h, float& m) {
    h = __bfloat162float(__float2bfloat16_rn(v));
    m = v - h;
}
__device__ __forceinline__ uint32_t bfpair(float a, float b) {
    __nv_bfloat162 t = __floats2bfloat162_rn(a, b);
    return *reinterpret_cast<uint32_t*>(&t);
}
#define MMA(cc, aa, bb)                                                         \
    asm volatile("mma.sync.aligned.m16n8k16.row.col.f32.bf16.bf16.f32 "        \
                 "{%0,%1,%2,%3},{%4,%5,%6,%7},{%8,%9},{%0,%1,%2,%3};"          \
                 : "+f"((cc)[0]), "+f"((cc)[1]), "+f"((cc)[2]), "+f"((cc)[3])  \
                 : "r"((aa)[0]), "r"((aa)[1]), "r"((aa)[2]), "r"((aa)[3]),     \
                   "r"((bb)[0]), "r"((bb)[1]))

// ---------------------------------------------------------------------------
// Kernel B: approximate sim -> per-row top-12 candidate indices.
// CTA: 64 t-rows x full s sweep (16 tiles of 128).  256 thr = 8 warps (1m x
// 8n), warp tile 64x16.  2 planes (h,m), 3 MMA terms (hh, hm, mh).
// ---------------------------------------------------------------------------
#define QPL 4160    // u32 per Q plane (64 x 65)
#define KPL 8320    // u32 per K plane (128 x 65)
#define SIM_SMEM ((2*QPL + 2*KPL) * 4 + 64 * 130 * 4)   // 99840+33280=133120

__global__ __launch_bounds__(256, 1) void simc_kernel()
{
    extern __shared__ uint32_t sm[];
    uint32_t* Qp = sm;
    uint32_t* Kp = sm + 2 * QPL;
    float* stage = reinterpret_cast<float*>(sm + 2 * QPL + 2 * KPL);

    const int tid  = threadIdx.x;
    const int lane = tid & 31;
    const int grp  = lane >> 2, tig = lane & 3;
    const int wn   = tid >> 5;
    const int b    = blockIdx.y;
    const int t0   = blockIdx.x * 64;

    // Q planes (persistent): 64 rows x 128 k
#pragma unroll
    for (int l = 0; l < 8; l++) {
        int e = tid + l * 256;
        int row = e >> 5, c4 = e & 31;
        float4 v = *reinterpret_cast<const float4*>(
            &g_q[((size_t)(b * T_ + t0 + row)) * KQ_ + c4 * 4]);
        float h0,m0,h1,m1,h2,m2,h3,m3;
        split2f(v.x,h0,m0); split2f(v.y,h1,m1);
        split2f(v.z,h2,m2); split2f(v.w,h3,m3);
        int idx = row * 65 + c4 * 2;
        Qp[0*QPL+idx] = bfpair(h0,h1);  Qp[0*QPL+idx+1] = bfpair(h2,h3);
        Qp[1*QPL+idx] = bfpair(m0,m1);  Qp[1*QPL+idx+1] = bfpair(m2,m3);
    }

    float topv[TOPN];
    int   topi[TOPN];
#pragma unroll
    for (int j = 0; j < TOPN; j++) { topv[j] = -3.402823466e38f; topi[j] = 0x7FFFFFFF; }

    for (int st = 0; st < 16; st++) {
        __syncthreads();
        // K planes: 128 s-rows x 128 k
#pragma unroll
        for (int l = 0; l < 16; l++) {
            int e = tid + l * 256;
            int row = e >> 5, c4 = e & 31;
            float4 v = *reinterpret_cast<const float4*>(
                &g_k[((size_t)(b * T_ + st * 128 + row)) * KQ_ + c4 * 4]);
            float h0,m0,h1,m1,h2,m2,h3,m3;
            split2f(v.x,h0,m0); split2f(v.y,h1,m1);
            split2f(v.z,h2,m2); split2f(v.w,h3,m3);
            int idx = row * 65 + c4 * 2;
            Kp[0*KPL+idx] = bfpair(h0,h1);  Kp[0*KPL+idx+1] = bfpair(h2,h3);
            Kp[1*KPL+idx] = bfpair(m0,m1);  Kp[1*KPL+idx+1] = bfpair(m2,m3);
        }
        __syncthreads();

        float c[4][2][4];
#pragma unroll
        for (int i = 0; i < 4; i++)
#pragma unroll
            for (int j = 0; j < 2; j++)
#pragma unroll
                for (int e = 0; e < 4; e++) c[i][j][e] = 0.f;

#pragma unroll
        for (int kk = 0; kk < 8; kk++) {
            uint32_t a[2][4][4];
#pragma unroll
            for (int p = 0; p < 2; p++)
#pragma unroll
                for (int mt = 0; mt < 4; mt++) {
                    int rb = (mt * 16 + grp) * 65 + kk * 8 + tig;
                    a[p][mt][0] = Qp[p*QPL + rb];
                    a[p][mt][1] = Qp[p*QPL + rb + 8 * 65];
                    a[p][mt][2] = Qp[p*QPL + rb + 4];
                    a[p][mt][3] = Qp[p*QPL + rb + 8 * 65 + 4];
                }
#pragma unroll
            for (int nt = 0; nt < 2; nt++) {
                uint32_t bfr[2][2];
                int nb = (wn * 16 + nt * 8 + grp) * 65 + kk * 8 + tig;
#pragma unroll
                for (int p = 0; p < 2; p++) {
                    bfr[p][0] = Kp[p*KPL + nb];
                    bfr[p][1] = Kp[p*KPL + nb + 4];
                }
#pragma unroll
                for (int mt = 0; mt < 4; mt++) {
                    MMA(c[mt][nt], a[0][mt], bfr[0]);   // h·h
                    MMA(c[mt][nt], a[0][mt], bfr[1]);   // h·m
                    MMA(c[mt][nt], a[1][mt], bfr[0]);   // m·h
                }
            }
        }

        // dump approx sims to stage[t][s]
#pragma unroll
        for (int mt = 0; mt < 4; mt++)
#pragma unroll
            for (int nt = 0; nt < 2; nt++) {
                int t = mt * 16 + grp;
                int s = wn * 16 + nt * 8 + 2 * tig;
                *reinterpret_cast<float2*>(&stage[t * 130 + s]) =
                    make_float2(c[mt][nt][0], c[mt][nt][1]);
                *reinterpret_cast<float2*>(&stage[(t + 8) * 130 + s]) =
                    make_float2(c[mt][nt][2], c[mt][nt][3]);
            }
        __syncthreads();

        // fold: 4 threads/row, each scans 32 approx sims
        {
            int row = tid >> 2, qtr = tid & 3;
            int sb = st * 128 + qtr * 32;
            const float2* sr = reinterpret_cast<const float2*>(
                &stage[row * 130 + qtr * 32]);
#pragma unroll 4
            for (int j = 0; j < 16; j++) {
                float2 v = sr[j];
                if (fmaxf(v.x, v.y) > topv[TOPN - 1]) {
                    if (v.x > topv[TOPN - 1]) {
                        topv[TOPN-1] = v.x; topi[TOPN-1] = sb + 2*j;
#pragma unroll
                        for (int p = TOPN-1; p > 0; p--)
                            if (topv[p] > topv[p-1]) {
                                float tv=topv[p]; topv[p]=topv[p-1]; topv[p-1]=tv;
                                int   ti=topi[p]; topi[p]=topi[p-1]; topi[p-1]=ti;
                            }
                    }
                    if (v.y > topv[TOPN - 1]) {
                        topv[TOPN-1] = v.y; topi[TOPN-1] = sb + 2*j + 1;
#pragma unroll
                        for (int p = TOPN-1; p > 0; p--)
                            if (topv[p] > topv[p-1]) {
                                float tv=topv[p]; topv[p]=topv[p-1]; topv[p-1]=tv;
                                int   ti=topi[p]; topi[p]=topi[p-1]; topi[p-1]=ti;
                            }
                    }
                }
            }
        }
    }

    // merge 4 per-quarter lists -> per-row top-12 candidate indices
    __syncthreads();
#pragma unroll
    for (int j = 0; j < TOPN; j++) {
        stage[tid * 26 + j] = topv[j];
        reinterpret_cast<int*>(stage)[tid * 26 + TOPN + j] = topi[j];
    }
    __syncthreads();

#pragma unroll
    for (int stride = 1; stride <= 2; stride <<= 1) {
        if ((tid & (2 * stride - 1)) == 0) {
            float v0[TOPN], v1[TOPN];
            int   i0[TOPN], i1[TOPN];
#pragma unroll
            for (int j = 0; j < TOPN; j++) {
                v0[j] = stage[tid * 26 + j];
                i0[j] = reinterpret_cast<int*>(stage)[tid * 26 + TOPN + j];
                v1[j] = stage[(tid + stride) * 26 + j];
                i1[j] = reinterpret_cast<int*>(stage)[(tid + stride) * 26 + TOPN + j];
            }
            float mv[TOPN]; int mi[TOPN];
            int p = 0, q = 0;
#pragma unroll
            for (int j = 0; j < TOPN; j++) {
                bool take0 = (q >= TOPN) ||
                    (p < TOPN && (v0[p] > v1[q] ||
                                  (v0[p] == v1[q] && i0[p] < i1[q])));
                mv[j] = take0 ? v0[p] : v1[q];
                mi[j] = take0 ? i0[p] : i1[q];
                if (take0) p++; else q++;
            }
#pragma unroll
            for (int j = 0; j < TOPN; j++) {
                stage[tid * 26 + j] = mv[j];
                reinterpret_cast<int*>(stage)[tid * 26 + TOPN + j] = mi[j];
            }
        }
        __syncthreads();
    }

    if ((tid & 3) == 0) {
        size_t rowg = (size_t)b * T_ + t0 + (tid >> 2);
#pragma unroll
        for (int j = 0; j < TOPN; j++)
            g_cand[rowg * TOPN + j] =
                reinterpret_cast<int*>(stage)[tid * 26 + TOPN + j];
    }
}

// ---------------------------------------------------------------------------
// Kernel R: rescore.  Per t-row: exact fp32 sims for the 12 candidates using
// R1's FMA order (d-ascending chain) -> bit-identical values -> select top-8
// by (value desc, index asc), matching R1's scan-insert semantics.
// ---------------------------------------------------------------------------
__global__ __launch_bounds__(32) void rescore_kernel(float* __restrict__ out)
{
    const int row  = blockIdx.x;          // 0..BT_-1
    const int b    = row >> 11;           // /T_
    const int lane = threadIdx.x;

    __shared__ float4 qs[32];
    __shared__ float  sv[32];
    __shared__ int    si[32];

    qs[lane] = reinterpret_cast<const float4*>(&g_q[(size_t)row * KQ_])[lane];
    __syncwarp();

    float v = -3.402823466e38f;
    int   s = 0x7FFFFFFF;
    if (lane < TOPN) {
        s = g_cand[(size_t)row * TOPN + lane];
        const float4* kr = reinterpret_cast<const float4*>(
            &g_k[((size_t)(b << 11) + s) * KQ_]);
        float acc = 0.f;
#pragma unroll
        for (int d4 = 0; d4 < 32; d4++) {
            float4 kv = kr[d4];
            float4 qv = qs[d4];
            acc = fmaf(qv.x, kv.x, acc);
            acc = fmaf(qv.y, kv.y, acc);
            acc = fmaf(qv.z, kv.z, acc);
            acc = fmaf(qv.w, kv.w, acc);
        }
        v = acc;
    }
    sv[lane] = v;
    si[lane] = s;
    __syncwarp();

    if (lane == 0) {
        float tv[TOPK]; int ti[TOPK];
#pragma unroll
        for (int j = 0; j < TOPK; j++) { tv[j] = -3.402823466e38f; ti[j] = 0x7FFFFFFF; }
        for (int e = 0; e < TOPN; e++) {
            float vv = sv[e]; int id = si[e];
            bool better = (vv > tv[TOPK-1]) || (vv == tv[TOPK-1] && id < ti[TOPK-1]);
            if (better) {
                tv[TOPK-1] = vv; ti[TOPK-1] = id;
#pragma unroll
                for (int p = TOPK-1; p > 0; p--) {
                    bool up = (tv[p] > tv[p-1]) ||
                              (tv[p] == tv[p-1] && ti[p] < ti[p-1]);
                    if (up) {
                        float a = tv[p]; tv[p] = tv[p-1]; tv[p-1] = a;
                        int   c = ti[p]; ti[p] = ti[p-1]; ti[p-1] = c;
                    }
                }
            }
        }
        const float scale = 0.08838834764831843f;   // 1/sqrt(128)
        float* out_idx = out + GATH_N;
        float* out_sim = out + GATH_N + IDX_N;
#pragma unroll
        for (int j = 0; j < TOPK; j++) {
            g_idx[(size_t)row * TOPK + j]   = ti[j];
            out_idx[(size_t)row * TOPK + j] = (float)ti[j];
            out_sim[(size_t)row * TOPK + j] = tv[j] * scale;
        }
    }
}

// ---------------------------------------------------------------------------
// Kernel C: gather.  One block per (b,t,j) row; 512MB stores, L2-hit reads.
// ---------------------------------------------------------------------------
__global__ __launch_bounds__(256) void gather_kernel(
    const float* __restrict__ x, float* __restrict__ out)
{
    int r = blockIdx.x;
    int b = r >> 14;                       // r / (T_*TOPK)
    int src_t = g_idx[r];
    const float4* src = reinterpret_cast<const float4*>(
        &x[((size_t)b * T_ + src_t) * D_]);
    float4* dst = reinterpret_cast<float4*>(&out[(size_t)r * D_]);
    dst[threadIdx.x] = src[threadIdx.x];
}

// ---------------------------------------------------------------------------
extern "C" void kernel_launch(void* const* d_in, const int* in_sizes, int n_in,
                              void* d_out, int out_size)
{
    const float* x  = (const float*)d_in[0];
    const float* Wq = (const float*)d_in[1];
    const float* bq = (const float*)d_in[2];
    const float* Wk = (const float*)d_in[3];
    const float* bk = (const float*)d_in[4];
    float* out = (float*)d_out;

    cudaFuncSetAttribute(simc_kernel,
                         cudaFuncAttributeMaxDynamicSharedMemorySize, SIM_SMEM);

    proj_kernel<<<BT_ / 64, 256>>>(x, Wq, bq, Wk, bk);

    dim3 gridB(T_ / 64, B_);
    simc_kernel<<<gridB, 256, SIM_SMEM>>>();

    rescore_kernel<<<BT_, 32>>>(out);

    gather_kernel<<<BT_ * TOPK, 256>>>(x, out);
}

// round 9
// speedup vs baseline: 1.1718x; 1.1718x over previous
#include <cuda_runtime.h>
#include <cuda_bf16.h>
#include <stdint.h>

#define B_   8
#define T_   2048
#define D_   1024
#define KQ_  128
#define TOPK 8
#define TOPN 16            // approx candidates tracked per row
#define BT_  (B_ * T_)

#define GATH_N ((size_t)BT_ * TOPK * D_)   // 134217728
#define IDX_N  ((size_t)BT_ * TOPK)        // 131072

// Scratch (__device__ globals; allocation-free rule)
__device__ float    g_q[BT_ * KQ_];
__device__ float    g_k[BT_ * KQ_];
__device__ uint32_t g_qh[BT_ * (KQ_ / 2)];   // bf16 h-plane, 2 per u32
__device__ uint32_t g_kh[BT_ * (KQ_ / 2)];
__device__ int      g_idx[BT_ * TOPK];
__device__ int      g_cand[BT_ * TOPN];

__device__ __forceinline__ uint32_t bfpair(float a, float b) {
    __nv_bfloat162 t = __floats2bfloat162_rn(a, b);
    return *reinterpret_cast<uint32_t*>(&t);
}

#define MMA(cc, aa, bb)                                                         \
    asm volatile("mma.sync.aligned.m16n8k16.row.col.f32.bf16.bf16.f32 "        \
                 "{%0,%1,%2,%3},{%4,%5,%6,%7},{%8,%9},{%0,%1,%2,%3};"          \
                 : "+f"((cc)[0]), "+f"((cc)[1]), "+f"((cc)[2]), "+f"((cc)[3])  \
                 : "r"((aa)[0]), "r"((aa)[1]), "r"((aa)[2]), "r"((aa)[3]),     \
                   "r"((bb)[0]), "r"((bb)[1]))

// ---------------------------------------------------------------------------
// Kernel A: proj — R1's kernel verbatim (bit-identical q/k; known-good draw),
// plus bf16 h-plane emission in the epilogue (does not touch fp32 path).
// ---------------------------------------------------------------------------
__global__ __launch_bounds__(256) void proj_kernel(
    const float* __restrict__ x,
    const float* __restrict__ Wq, const float* __restrict__ bq,
    const float* __restrict__ Wk, const float* __restrict__ bk)
{
    __shared__ float As[32][68];
    __shared__ float Bs[32][260];

    const int tid = threadIdx.x;
    const int m0  = blockIdx.x * 64;
    const int ty  = tid >> 5;
    const int tx  = tid & 31;

    float acc[8][8];
#pragma unroll
    for (int i = 0; i < 8; i++)
#pragma unroll
        for (int j = 0; j < 8; j++) acc[i][j] = 0.f;

    for (int k0 = 0; k0 < D_; k0 += 32) {
#pragma unroll
        for (int l = 0; l < 2; l++) {
            int e  = tid + l * 256;
            int r  = e >> 3;
            int c4 = e & 7;
            float4 v = *reinterpret_cast<const float4*>(
                &x[(size_t)(m0 + r) * D_ + k0 + c4 * 4]);
            As[c4 * 4 + 0][r] = v.x;
            As[c4 * 4 + 1][r] = v.y;
            As[c4 * 4 + 2][r] = v.z;
            As[c4 * 4 + 3][r] = v.w;
        }
#pragma unroll
        for (int l = 0; l < 8; l++) {
            int e  = tid + l * 256;
            int n  = e >> 3;
            int c4 = e & 7;
            const float* Wsrc = (n < 128) ? &Wq[(size_t)n * D_]
                                          : &Wk[(size_t)(n - 128) * D_];
            float4 v = *reinterpret_cast<const float4*>(&Wsrc[k0 + c4 * 4]);
            Bs[c4 * 4 + 0][n] = v.x;
            Bs[c4 * 4 + 1][n] = v.y;
            Bs[c4 * 4 + 2][n] = v.z;
            Bs[c4 * 4 + 3][n] = v.w;
        }
        __syncthreads();

#pragma unroll 4
        for (int d = 0; d < 32; d++) {
            float4 a0 = *reinterpret_cast<const float4*>(&As[d][ty * 8]);
            float4 a1 = *reinterpret_cast<const float4*>(&As[d][ty * 8 + 4]);
            float4 b0 = *reinterpret_cast<const float4*>(&Bs[d][tx * 8]);
            float4 b1 = *reinterpret_cast<const float4*>(&Bs[d][tx * 8 + 4]);
            float a[8] = {a0.x, a0.y, a0.z, a0.w, a1.x, a1.y, a1.z, a1.w};
            float b[8] = {b0.x, b0.y, b0.z, b0.w, b1.x, b1.y, b1.z, b1.w};
#pragma unroll
            for (int i = 0; i < 8; i++)
#pragma unroll
                for (int j = 0; j < 8; j++) acc[i][j] += a[i] * b[j];
        }
        __syncthreads();
    }

    float* dst;
    uint32_t* hdst;
    const float* bias;
    int n0;
    if (tx < 16) { dst = g_q; hdst = g_qh; bias = bq; n0 = tx * 8; }
    else         { dst = g_k; hdst = g_kh; bias = bk; n0 = (tx - 16) * 8; }
    float bb[8];
#pragma unroll
    for (int j = 0; j < 8; j++) bb[j] = bias[n0 + j];

#pragma unroll
    for (int i = 0; i < 8; i++) {
        int m = m0 + ty * 8 + i;
        float4 v0 = make_float4(acc[i][0] + bb[0], acc[i][1] + bb[1],
                                acc[i][2] + bb[2], acc[i][3] + bb[3]);
        float4 v1 = make_float4(acc[i][4] + bb[4], acc[i][5] + bb[5],
                                acc[i][6] + bb[6], acc[i][7] + bb[7]);
        *reinterpret_cast<float4*>(&dst[(size_t)m * KQ_ + n0])     = v0;
        *reinterpret_cast<float4*>(&dst[(size_t)m * KQ_ + n0 + 4]) = v1;
        // bf16 h-plane for candidate pass
        uint4 hv = make_uint4(bfpair(v0.x, v0.y), bfpair(v0.z, v0.w),
                              bfpair(v1.x, v1.y), bfpair(v1.z, v1.w));
        *reinterpret_cast<uint4*>(&hdst[(size_t)m * 64 + (n0 >> 1)]) = hv;
    }
}

// ---------------------------------------------------------------------------
// Kernel B: candidate pass.  Approx sim = bf16(q)·bf16(k)^T (1 MMA term,
// err std ~0.02 << rank8->rank16 gap).  CTA: 64 t-rows x 16 s-tiles of 128.
// 256 thr = 8 warps (1m x 8n).  2 CTAs/SM: fold overlaps other CTA's MMA.
// Per-row fold by one thread -> top-16 candidate indices.
// ---------------------------------------------------------------------------
#define QST 68                       // u32 row stride (conflict-free, 16B-aligned)
#define QPL (64 * QST)               // 4352 u32
#define KPL (128 * QST)              // 8704 u32
#define SST 132                      // stage stride in f32 (multiple of 4!)
#define SIM_SMEM ((QPL + KPL) * 4 + 64 * SST * 4)   // 52224 + 33792 = 86016

__global__ __launch_bounds__(256, 2) void simc_kernel()
{
    extern __shared__ uint32_t sm[];
    uint32_t* Qp = sm;
    uint32_t* Kp = sm + QPL;
    float* stage = reinterpret_cast<float*>(sm + QPL + KPL);

    const int tid  = threadIdx.x;
    const int lane = tid & 31;
    const int grp  = lane >> 2, tig = lane & 3;
    const int wn   = tid >> 5;
    const int b    = blockIdx.y;
    const int t0   = blockIdx.x * 64;

    // Q plane (persistent): 64 rows x 128 bf16 (16 uint4/row)
    {
        const uint4* src = reinterpret_cast<const uint4*>(
            &g_qh[((size_t)b * T_ + t0) * 64]);
#pragma unroll
        for (int l = 0; l < 4; l++) {
            int e = tid + l * 256;          // 0..1023
            int row = e >> 4, c8 = e & 15;
            *reinterpret_cast<uint4*>(&Qp[row * QST + c8 * 4]) = src[e];
        }
    }

    float topv[TOPN];
    int   topi[TOPN];
#pragma unroll
    for (int j = 0; j < TOPN; j++) { topv[j] = -3.402823466e38f; topi[j] = 0x7FFFFFFF; }

    for (int st = 0; st < 16; st++) {
        __syncthreads();   // stage reads done; Kp overwrite safe
        {
            const uint4* src = reinterpret_cast<const uint4*>(
                &g_kh[((size_t)b * T_ + st * 128) * 64]);
#pragma unroll
            for (int l = 0; l < 8; l++) {
                int e = tid + l * 256;      // 0..2047
                int row = e >> 4, c8 = e & 15;
                *reinterpret_cast<uint4*>(&Kp[row * QST + c8 * 4]) = src[e];
            }
        }
        __syncthreads();

        float c[4][2][4];
#pragma unroll
        for (int i = 0; i < 4; i++)
#pragma unroll
            for (int j = 0; j < 2; j++)
#pragma unroll
                for (int e = 0; e < 4; e++) c[i][j][e] = 0.f;

#pragma unroll
        for (int kk = 0; kk < 8; kk++) {
            uint32_t a[4][4];
#pragma unroll
            for (int mt = 0; mt < 4; mt++) {
                int rb = (mt * 16 + grp) * QST + kk * 8 + tig;
                a[mt][0] = Qp[rb];
                a[mt][1] = Qp[rb + 8 * QST];
                a[mt][2] = Qp[rb + 4];
                a[mt][3] = Qp[rb + 8 * QST + 4];
            }
#pragma unroll
            for (int nt = 0; nt < 2; nt++) {
                uint32_t bfr[2];
                int nb = (wn * 16 + nt * 8 + grp) * QST + kk * 8 + tig;
                bfr[0] = Kp[nb];
                bfr[1] = Kp[nb + 4];
#pragma unroll
                for (int mt = 0; mt < 4; mt++)
                    MMA(c[mt][nt], a[mt], bfr);
            }
        }

        // dump approx sims to stage[t][s] (stride SST)
#pragma unroll
        for (int mt = 0; mt < 4; mt++)
#pragma unroll
            for (int nt = 0; nt < 2; nt++) {
                int t = mt * 16 + grp;
                int s = wn * 16 + nt * 8 + 2 * tig;
                *reinterpret_cast<float2*>(&stage[t * SST + s]) =
                    make_float2(c[mt][nt][0], c[mt][nt][1]);
                *reinterpret_cast<float2*>(&stage[(t + 8) * SST + s]) =
                    make_float2(c[mt][nt][2], c[mt][nt][3]);
            }
        __syncthreads();

        // fold: thread r (<64) owns t-row r, scans 128 sims (32 float4)
        if (tid < 64) {
            const float4* sr = reinterpret_cast<const float4*>(&stage[tid * SST]);
            int sb = st * 128;
#pragma unroll 4
            for (int i = 0; i < 32; i++) {
                float4 v = sr[i];
                float mx = fmaxf(fmaxf(v.x, v.y), fmaxf(v.z, v.w));
                if (mx > topv[TOPN - 1]) {   // rare path
                    float vv[4] = {v.x, v.y, v.z, v.w};
#pragma unroll
                    for (int e = 0; e < 4; e++) {
                        if (vv[e] > topv[TOPN - 1]) {
                            topv[TOPN-1] = vv[e]; topi[TOPN-1] = sb + i * 4 + e;
#pragma unroll
                            for (int p = TOPN-1; p > 0; p--)
                                if (topv[p] > topv[p-1]) {
                                    float tv=topv[p]; topv[p]=topv[p-1]; topv[p-1]=tv;
                                    int   ti=topi[p]; topi[p]=topi[p-1]; topi[p-1]=ti;
                                }
                        }
                    }
                }
            }
        }
    }

    if (tid < 64) {
        size_t rowg = (size_t)b * T_ + t0 + tid;
#pragma unroll
        for (int j = 0; j < TOPN; j++)
            g_cand[rowg * TOPN + j] = topi[j];
    }
}

// ---------------------------------------------------------------------------
// Kernel R: rescore.  Warp per t-row (8 warps/block): exact fp32 sims for 16
// candidates in R1's FMA order (d-ascending chain -> bit-identical values),
// select top-8 by (value desc, index asc) == R1 scan-insert semantics.
// ---------------------------------------------------------------------------
__global__ __launch_bounds__(256) void rescore_kernel(float* __restrict__ out)
{
    const int tid  = threadIdx.x;
    const int w    = tid >> 5, lane = tid & 31;
    const int row  = blockIdx.x * 8 + w;
    const int b    = row >> 11;

    __shared__ float4 qs[8][32];
    __shared__ float  sv[8][TOPN];
    __shared__ int    si[8][TOPN];

    qs[w][lane] = reinterpret_cast<const float4*>(&g_q[(size_t)row * KQ_])[lane];
    __syncwarp();

    if (lane < TOPN) {
        int s = g_cand[(size_t)row * TOPN + lane];
        const float4* kr = reinterpret_cast<const float4*>(
            &g_k[((size_t)(b << 11) + s) * KQ_]);
        float acc = 0.f;
#pragma unroll
        for (int d4 = 0; d4 < 32; d4++) {
            float4 kv = kr[d4];
            float4 qv = qs[w][d4];
            acc = fmaf(qv.x, kv.x, acc);
            acc = fmaf(qv.y, kv.y, acc);
            acc = fmaf(qv.z, kv.z, acc);
            acc = fmaf(qv.w, kv.w, acc);
        }
        sv[w][lane] = acc;
        si[w][lane] = s;
    }
    __syncwarp();

    if (lane == 0) {
        float tv[TOPK]; int ti[TOPK];
#pragma unroll
        for (int j = 0; j < TOPK; j++) { tv[j] = -3.402823466e38f; ti[j] = 0x7FFFFFFF; }
        for (int e = 0; e < TOPN; e++) {
            float vv = sv[w][e]; int id = si[w][e];
            bool better = (vv > tv[TOPK-1]) || (vv == tv[TOPK-1] && id < ti[TOPK-1]);
            if (better) {
                tv[TOPK-1] = vv; ti[TOPK-1] = id;
#pragma unroll
                for (int p = TOPK-1; p > 0; p--) {
                    bool up = (tv[p] > tv[p-1]) ||
                              (tv[p] == tv[p-1] && ti[p] < ti[p-1]);
                    if (up) {
                        float a = tv[p]; tv[p] = tv[p-1]; tv[p-1] = a;
                        int   c = ti[p]; ti[p] = ti[p-1]; ti[p-1] = c;
                    }
                }
            }
        }
        const float scale = 0.08838834764831843f;   // 1/sqrt(128)
        float* out_idx = out + GATH_N;
        float* out_sim = out + GATH_N + IDX_N;
#pragma unroll
        for (int j = 0; j < TOPK; j++) {
            g_idx[(size_t)row * TOPK + j]   = ti[j];
            out_idx[(size_t)row * TOPK + j] = (float)ti[j];
            out_sim[(size_t)row * TOPK + j] = tv[j] * scale;
        }
    }
}

// ---------------------------------------------------------------------------
// Kernel C: gather.  Block per (b,t); copies 8 routed rows with streaming
// stores (dst never re-read -> keep L2 for x).
// ---------------------------------------------------------------------------
__global__ __launch_bounds__(256) void gather_kernel(
    const float* __restrict__ x, float* __restrict__ out)
{
    int bt = blockIdx.x;                  // 0..BT_-1
    int b  = bt >> 11;
    const float4* xb = reinterpret_cast<const float4*>(x) + (size_t)(b << 11) * 256;
    float4* dst = reinterpret_cast<float4*>(out) + (size_t)bt * TOPK * 256;
#pragma unroll
    for (int j = 0; j < TOPK; j++) {
        int src_t = g_idx[bt * TOPK + j];
        float4 v = __ldg(&xb[(size_t)src_t * 256 + threadIdx.x]);
        __stcs(&dst[(size_t)j * 256 + threadIdx.x], v);
    }
}

// ---------------------------------------------------------------------------
extern "C" void kernel_launch(void* const* d_in, const int* in_sizes, int n_in,
                              void* d_out, int out_size)
{
    const float* x  = (const float*)d_in[0];
    const float* Wq = (const float*)d_in[1];
    const float* bq = (const float*)d_in[2];
    const float* Wk = (const float*)d_in[3];
    const float* bk = (const float*)d_in[4];
    float* out = (float*)d_out;

    cudaFuncSetAttribute(simc_kernel,
                         cudaFuncAttributeMaxDynamicSharedMemorySize, SIM_SMEM);

    proj_kernel<<<BT_ / 64, 256>>>(x, Wq, bq, Wk, bk);

    dim3 gridB(T_ / 64, B_);
    simc_kernel<<<gridB, 256, SIM_SMEM>>>();

    rescore_kernel<<<BT_ / 8, 256>>>(out);

    gather_kernel<<<BT_, 256>>>(x, out);
}

// round 10
// speedup vs baseline: 1.4625x; 1.2480x over previous
#include <cuda_runtime.h>
#include <cuda_bf16.h>
#include <stdint.h>

#define B_   8
#define T_   2048
#define D_   1024
#define KQ_  128
#define TOPK 8
#define LK   8              // per-lane top-8 (exactness guarantee)
#define NC   64             // candidates per row (4 lanes x 2 halves x 8)
#define BT_  (B_ * T_)

#define GATH_N ((size_t)BT_ * TOPK * D_)   // 134217728
#define IDX_N  ((size_t)BT_ * TOPK)        // 131072

// Scratch (__device__ globals; allocation-free rule)
__device__ float    g_q[BT_ * KQ_];
__device__ float    g_k[BT_ * KQ_];
__device__ uint32_t g_qh[BT_ * (KQ_ / 2)];   // bf16 h-plane, 2 per u32
__device__ uint32_t g_kh[BT_ * (KQ_ / 2)];
__device__ int      g_idx[BT_ * TOPK];
__device__ int      g_cand[BT_ * NC];

__device__ __forceinline__ uint32_t bfpair(float a, float b) {
    __nv_bfloat162 t = __floats2bfloat162_rn(a, b);
    return *reinterpret_cast<uint32_t*>(&t);
}

#define MMA(cc, aa, bb)                                                         \
    asm volatile("mma.sync.aligned.m16n8k16.row.col.f32.bf16.bf16.f32 "        \
                 "{%0,%1,%2,%3},{%4,%5,%6,%7},{%8,%9},{%0,%1,%2,%3};"          \
                 : "+f"((cc)[0]), "+f"((cc)[1]), "+f"((cc)[2]), "+f"((cc)[3])  \
                 : "r"((aa)[0]), "r"((aa)[1]), "r"((aa)[2]), "r"((aa)[3]),     \
                   "r"((bb)[0]), "r"((bb)[1]))

// ---------------------------------------------------------------------------
// Kernel A: proj — R1's kernel verbatim (bit-identical q/k; known-good draw),
// plus bf16 h-plane emission in the epilogue.
// ---------------------------------------------------------------------------
__global__ __launch_bounds__(256) void proj_kernel(
    const float* __restrict__ x,
    const float* __restrict__ Wq, const float* __restrict__ bq,
    const float* __restrict__ Wk, const float* __restrict__ bk)
{
    __shared__ float As[32][68];
    __shared__ float Bs[32][260];

    const int tid = threadIdx.x;
    const int m0  = blockIdx.x * 64;
    const int ty  = tid >> 5;
    const int tx  = tid & 31;

    float acc[8][8];
#pragma unroll
    for (int i = 0; i < 8; i++)
#pragma unroll
        for (int j = 0; j < 8; j++) acc[i][j] = 0.f;

    for (int k0 = 0; k0 < D_; k0 += 32) {
#pragma unroll
        for (int l = 0; l < 2; l++) {
            int e  = tid + l * 256;
            int r  = e >> 3;
            int c4 = e & 7;
            float4 v = *reinterpret_cast<const float4*>(
                &x[(size_t)(m0 + r) * D_ + k0 + c4 * 4]);
            As[c4 * 4 + 0][r] = v.x;
            As[c4 * 4 + 1][r] = v.y;
            As[c4 * 4 + 2][r] = v.z;
            As[c4 * 4 + 3][r] = v.w;
        }
#pragma unroll
        for (int l = 0; l < 8; l++) {
            int e  = tid + l * 256;
            int n  = e >> 3;
            int c4 = e & 7;
            const float* Wsrc = (n < 128) ? &Wq[(size_t)n * D_]
                                          : &Wk[(size_t)(n - 128) * D_];
            float4 v = *reinterpret_cast<const float4*>(&Wsrc[k0 + c4 * 4]);
            Bs[c4 * 4 + 0][n] = v.x;
            Bs[c4 * 4 + 1][n] = v.y;
            Bs[c4 * 4 + 2][n] = v.z;
            Bs[c4 * 4 + 3][n] = v.w;
        }
        __syncthreads();

#pragma unroll 4
        for (int d = 0; d < 32; d++) {
            float4 a0 = *reinterpret_cast<const float4*>(&As[d][ty * 8]);
            float4 a1 = *reinterpret_cast<const float4*>(&As[d][ty * 8 + 4]);
            float4 b0 = *reinterpret_cast<const float4*>(&Bs[d][tx * 8]);
            float4 b1 = *reinterpret_cast<const float4*>(&Bs[d][tx * 8 + 4]);
            float a[8] = {a0.x, a0.y, a0.z, a0.w, a1.x, a1.y, a1.z, a1.w};
            float b[8] = {b0.x, b0.y, b0.z, b0.w, b1.x, b1.y, b1.z, b1.w};
#pragma unroll
            for (int i = 0; i < 8; i++)
#pragma unroll
                for (int j = 0; j < 8; j++) acc[i][j] += a[i] * b[j];
        }
        __syncthreads();
    }

    float* dst;
    uint32_t* hdst;
    const float* bias;
    int n0;
    if (tx < 16) { dst = g_q; hdst = g_qh; bias = bq; n0 = tx * 8; }
    else         { dst = g_k; hdst = g_kh; bias = bk; n0 = (tx - 16) * 8; }
    float bb[8];
#pragma unroll
    for (int j = 0; j < 8; j++) bb[j] = bias[n0 + j];

#pragma unroll
    for (int i = 0; i < 8; i++) {
        int m = m0 + ty * 8 + i;
        float4 v0 = make_float4(acc[i][0] + bb[0], acc[i][1] + bb[1],
                                acc[i][2] + bb[2], acc[i][3] + bb[3]);
        float4 v1 = make_float4(acc[i][4] + bb[4], acc[i][5] + bb[5],
                                acc[i][6] + bb[6], acc[i][7] + bb[7]);
        *reinterpret_cast<float4*>(&dst[(size_t)m * KQ_ + n0])     = v0;
        *reinterpret_cast<float4*>(&dst[(size_t)m * KQ_ + n0 + 4]) = v1;
        uint4 hv = make_uint4(bfpair(v0.x, v0.y), bfpair(v0.z, v0.w),
                              bfpair(v1.x, v1.y), bfpair(v1.z, v1.w));
        *reinterpret_cast<uint4*>(&hdst[(size_t)m * 64 + (n0 >> 1)]) = hv;
    }
}

// ---------------------------------------------------------------------------
// Kernel B: candidate pass, fold-in-registers.
// Grid (16, 8, 2): x = 128-row t-tile, y = batch, z = s-half (1024 s each).
// 8 warps; warp w owns rows 16w..16w+15 for ALL 128 cols of each s-tile.
// Thread (grp,tig) owns rows {16w+grp, +8}, cols {nt*8+2tig+e}.  Per-lane
// per-row register top-8: true top-8 member has <=7 superiors row-wide, so
// it always survives in its lane's top-8 (deterministic set guarantee).
// ---------------------------------------------------------------------------
#define QST 68
#define TPL (128 * QST)                  // 8704 u32 per tile plane
#define SIM_SMEM (2 * TPL * 4)           // 69632 B

__global__ __launch_bounds__(256, 2) void simc_kernel()
{
    extern __shared__ uint32_t sm[];
    uint32_t* Qp = sm;
    uint32_t* Kp = sm + TPL;

    const int tid  = threadIdx.x;
    const int lane = tid & 31;
    const int grp  = lane >> 2, tig = lane & 3;
    const int w    = tid >> 5;
    const int b    = blockIdx.y;
    const int t0   = blockIdx.x * 128;
    const int half = blockIdx.z;

    // Q tile: 128 rows x 16 uint4 (once)
    {
        const uint4* src = reinterpret_cast<const uint4*>(
            &g_qh[((size_t)b * T_ + t0) * 64]);
#pragma unroll
        for (int l = 0; l < 8; l++) {
            int e = tid + l * 256;        // 0..2047
            int row = e >> 4, c8 = e & 15;
            *reinterpret_cast<uint4*>(&Qp[row * QST + c8 * 4]) = src[e];
        }
    }

    float tv0[LK], tv1[LK];
    int   ti0[LK], ti1[LK];
#pragma unroll
    for (int j = 0; j < LK; j++) {
        tv0[j] = -3.402823466e38f; ti0[j] = 0x7FFFFFFF;
        tv1[j] = -3.402823466e38f; ti1[j] = 0x7FFFFFFF;
    }

    const int rbA = (16 * w + grp) * QST;   // A-fragment row base (u32)

    for (int st = 0; st < 8; st++) {
        const int s0 = half * 1024 + st * 128;
        // K tile: 128 rows x 16 uint4
        {
            const uint4* src = reinterpret_cast<const uint4*>(
                &g_kh[((size_t)b * T_ + s0) * 64]);
#pragma unroll
            for (int l = 0; l < 8; l++) {
                int e = tid + l * 256;
                int row = e >> 4, c8 = e & 15;
                *reinterpret_cast<uint4*>(&Kp[row * QST + c8 * 4]) = src[e];
            }
        }
        __syncthreads();

        float c[16][4];
#pragma unroll
        for (int nt = 0; nt < 16; nt++)
#pragma unroll
            for (int e = 0; e < 4; e++) c[nt][e] = 0.f;

#pragma unroll
        for (int kk = 0; kk < 8; kk++) {
            uint32_t a[4];
            int ra = rbA + kk * 8 + tig;
            a[0] = Qp[ra];
            a[1] = Qp[ra + 8 * QST];
            a[2] = Qp[ra + 4];
            a[3] = Qp[ra + 8 * QST + 4];
#pragma unroll
            for (int nt = 0; nt < 16; nt++) {
                uint32_t bf[2];
                int rb = (nt * 8 + grp) * QST + kk * 8 + tig;
                bf[0] = Kp[rb];
                bf[1] = Kp[rb + 4];
                MMA(c[nt], a, bf);
            }
        }

        // fold in registers: c[nt] = rows {16w+grp,(+8)} x cols nt*8+2tig+{0,1}
#pragma unroll
        for (int nt = 0; nt < 16; nt++) {
            int sb = s0 + nt * 8 + 2 * tig;
#pragma unroll
            for (int e = 0; e < 2; e++) {
                float v = c[nt][e];
                if (v > tv0[LK - 1]) {
                    tv0[LK-1] = v; ti0[LK-1] = sb + e;
#pragma unroll
                    for (int p = LK-1; p > 0; p--)
                        if (tv0[p] > tv0[p-1]) {
                            float a_ = tv0[p]; tv0[p] = tv0[p-1]; tv0[p-1] = a_;
                            int   c_ = ti0[p]; ti0[p] = ti0[p-1]; ti0[p-1] = c_;
                        }
                }
            }
#pragma unroll
            for (int e = 0; e < 2; e++) {
                float v = c[nt][2 + e];
                if (v > tv1[LK - 1]) {
                    tv1[LK-1] = v; ti1[LK-1] = sb + e;
#pragma unroll
                    for (int p = LK-1; p > 0; p--)
                        if (tv1[p] > tv1[p-1]) {
                            float a_ = tv1[p]; tv1[p] = tv1[p-1]; tv1[p-1] = a_;
                            int   c_ = ti1[p]; ti1[p] = ti1[p-1]; ti1[p-1] = c_;
                        }
                }
            }
        }
        __syncthreads();   // MMA reads of Kp done before next overwrite
    }

    // write candidates: 4 lanes x 8 per row per half
    {
        size_t r0 = (size_t)b * T_ + t0 + 16 * w + grp;
        size_t r1 = r0 + 8;
        int base = half * 32 + tig * 8;
#pragma unroll
        for (int j = 0; j < LK; j++) {
            g_cand[r0 * NC + base + j] = ti0[j];
            g_cand[r1 * NC + base + j] = ti1[j];
        }
    }
}

// ---------------------------------------------------------------------------
// Kernel R: rescore.  Warp per t-row: exact fp32 sims for 64 candidates in
// R1's FMA order (d-ascending chain -> bit-identical values), select top-8
// by (value desc, index asc) == R1 scan-insert semantics.
// ---------------------------------------------------------------------------
__global__ __launch_bounds__(256) void rescore_kernel(float* __restrict__ out)
{
    const int tid  = threadIdx.x;
    const int w    = tid >> 5, lane = tid & 31;
    const int row  = blockIdx.x * 8 + w;
    const int b    = row >> 11;

    __shared__ float4 qs[8][32];
    __shared__ float  sv[8][NC];
    __shared__ int    si[8][NC];

    qs[w][lane] = reinterpret_cast<const float4*>(&g_q[(size_t)row * KQ_])[lane];
    __syncwarp();

    int s0 = g_cand[(size_t)row * NC + lane];
    int s1 = g_cand[(size_t)row * NC + 32 + lane];
    const float4* k0 = reinterpret_cast<const float4*>(
        &g_k[((size_t)(b << 11) + s0) * KQ_]);
    const float4* k1 = reinterpret_cast<const float4*>(
        &g_k[((size_t)(b << 11) + s1) * KQ_]);
    float a0 = 0.f, a1 = 0.f;
#pragma unroll
    for (int d4 = 0; d4 < 32; d4++) {
        float4 qv = qs[w][d4];
        float4 kv0 = k0[d4];
        float4 kv1 = k1[d4];
        a0 = fmaf(qv.x, kv0.x, a0); a0 = fmaf(qv.y, kv0.y, a0);
        a0 = fmaf(qv.z, kv0.z, a0); a0 = fmaf(qv.w, kv0.w, a0);
        a1 = fmaf(qv.x, kv1.x, a1); a1 = fmaf(qv.y, kv1.y, a1);
        a1 = fmaf(qv.z, kv1.z, a1); a1 = fmaf(qv.w, kv1.w, a1);
    }
    sv[w][lane] = a0;      si[w][lane] = s0;
    sv[w][lane + 32] = a1; si[w][lane + 32] = s1;
    __syncwarp();

    if (lane == 0) {
        float tv[TOPK]; int ti[TOPK];
#pragma unroll
        for (int j = 0; j < TOPK; j++) { tv[j] = -3.402823466e38f; ti[j] = 0x7FFFFFFF; }
        for (int e = 0; e < NC; e++) {
            float vv = sv[w][e]; int id = si[w][e];
            bool better = (vv > tv[TOPK-1]) || (vv == tv[TOPK-1] && id < ti[TOPK-1]);
            if (better) {
                tv[TOPK-1] = vv; ti[TOPK-1] = id;
#pragma unroll
                for (int p = TOPK-1; p > 0; p--) {
                    bool up = (tv[p] > tv[p-1]) ||
                              (tv[p] == tv[p-1] && ti[p] < ti[p-1]);
                    if (up) {
                        float a_ = tv[p]; tv[p] = tv[p-1]; tv[p-1] = a_;
                        int   c_ = ti[p]; ti[p] = ti[p-1]; ti[p-1] = c_;
                    }
                }
            }
        }
        const float scale = 0.08838834764831843f;   // 1/sqrt(128)
        float* out_idx = out + GATH_N;
        float* out_sim = out + GATH_N + IDX_N;
#pragma unroll
        for (int j = 0; j < TOPK; j++) {
            g_idx[(size_t)row * TOPK + j]   = ti[j];
            out_idx[(size_t)row * TOPK + j] = (float)ti[j];
            out_sim[(size_t)row * TOPK + j] = tv[j] * scale;
        }
    }
}

// ---------------------------------------------------------------------------
// Kernel C: gather.  Block per (b,t); streaming stores (dst never re-read).
// ---------------------------------------------------------------------------
__global__ __launch_bounds__(256) void gather_kernel(
    const float* __restrict__ x, float* __restrict__ out)
{
    int bt = blockIdx.x;                  // 0..BT_-1
    int b  = bt >> 11;
    const float4* xb = reinterpret_cast<const float4*>(x) + (size_t)(b << 11) * 256;
    float4* dst = reinterpret_cast<float4*>(out) + (size_t)bt * TOPK * 256;
#pragma unroll
    for (int j = 0; j < TOPK; j++) {
        int src_t = g_idx[bt * TOPK + j];
        float4 v = __ldg(&xb[(size_t)src_t * 256 + threadIdx.x]);
        __stcs(&dst[(size_t)j * 256 + threadIdx.x], v);
    }
}

// ---------------------------------------------------------------------------
extern "C" void kernel_launch(void* const* d_in, const int* in_sizes, int n_in,
                              void* d_out, int out_size)
{
    const float* x  = (const float*)d_in[0];
    const float* Wq = (const float*)d_in[1];
    const float* bq = (const float*)d_in[2];
    const float* Wk = (const float*)d_in[3];
    const float* bk = (const float*)d_in[4];
    float* out = (float*)d_out;

    cudaFuncSetAttribute(simc_kernel,
                         cudaFuncAttributeMaxDynamicSharedMemorySize, SIM_SMEM);

    proj_kernel<<<BT_ / 64, 256>>>(x, Wq, bq, Wk, bk);

    dim3 gridB(T_ / 128, B_, 2);
    simc_kernel<<<gridB, 256, SIM_SMEM>>>();

    rescore_kernel<<<BT_ / 8, 256>>>(out);

    gather_kernel<<<BT_, 256>>>(x, out);
}